// round 2
// baseline (speedup 1.0000x reference)
#include <cuda_runtime.h>
#include <cuda_bf16.h>
#include <math.h>
#include <stdint.h>

#define SEQ    70
#define BATCH  128
#define HID    512
#define VOCAB  10000
#define MB     (SEQ*BATCH)        /* 8960 */
#define BH     (BATCH*HID)        /* 65536 */
#define LOGITS ((size_t)MB*VOCAB) /* 89,600,000 */
#define NB_REC 32

// ---------------- device scratch (no runtime allocation allowed) -------------
__device__ float    g_G [MB*3*HID];     // 8960 x 1536
__device__ float    g_h0[SEQ*BH];
__device__ float    g_h1[SEQ*BH];
__device__ float    g_rh[BH];
__device__ volatile unsigned g_bar[160];

// ---------------- helpers ----------------------------------------------------
__device__ __forceinline__ float f2t(float x){
    unsigned u; asm("cvt.rna.tf32.f32 %0, %1;" : "=r"(u) : "f"(x));
    return __uint_as_float(u);
}
__device__ __forceinline__ unsigned bits(float x){ return __float_as_uint(x); }

__device__ __forceinline__ void mma8(float* c, const unsigned* a, unsigned b0, unsigned b1){
    asm volatile(
      "mma.sync.aligned.m16n8k8.row.col.f32.tf32.tf32.f32 "
      "{%0,%1,%2,%3},{%4,%5,%6,%7},{%8,%9},{%0,%1,%2,%3};\n"
      : "+f"(c[0]), "+f"(c[1]), "+f"(c[2]), "+f"(c[3])
      : "r"(a[0]), "r"(a[1]), "r"(a[2]), "r"(a[3]), "r"(b0), "r"(b1));
}
__device__ __forceinline__ float sigm(float x){ return 1.0f/(1.0f + expf(-x)); }

__global__ void zero_bars(){ if (threadIdx.x < 160) g_bar[threadIdx.x] = 0u; }

__device__ __forceinline__ void gridbar(int idx){
    __threadfence();
    __syncthreads();
    if (threadIdx.x == 0){
        atomicAdd((unsigned*)&g_bar[idx], 1u);
        while (g_bar[idx] < NB_REC) { }
        __threadfence();
    }
    __syncthreads();
}

// ============================================================================
// Generic tf32 GEMM: C[M,N] = A[M,512] @ B[512,N] + bias
// A optionally gathered: row r comes from gtab[gidx[r]].
// 128x128x32 tiles, 256 threads, 8 warps (2m x 4n), warp tile 64x32.
// ============================================================================
__global__ void __launch_bounds__(256) gemm_tf32(
    const float* __restrict__ A, const float* __restrict__ B,
    const float* __restrict__ bias, float* __restrict__ C, int N,
    const int* __restrict__ gidx, const float* __restrict__ gtab)
{
    extern __shared__ float sm[];
    float* sA = sm;              // [2][128][36]
    float* sB = sm + 2*128*36;   // [2][32][136]

    const int tid = threadIdx.x, w = tid>>5, lane = tid&31;
    const int ly = lane>>2, lx = lane&3;
    const int wm = w>>2, wn = w&3;
    const int bm = blockIdx.y*128, bn = blockIdx.x*128;

    // A loads: thread covers row (tid>>1), 16 k-floats at offset (tid&1)*16
    const int arl = tid>>1;
    const int akq = (tid&1)*16;
    const float* arow = gidx ? (gtab + (size_t)__ldg(gidx + bm + arl)*512)
                             : (A    + (size_t)(bm + arl)*512);
    // B loads: thread covers k-row (tid>>3), 16 n-floats at offset (tid&7)*16
    const int bkl = tid>>3, bnq = (tid&7)*16;

    float acc[4][4][4];
    #pragma unroll
    for (int i=0;i<4;i++) {
        #pragma unroll
        for (int j=0;j<4;j++) {
            #pragma unroll
            for (int k=0;k<4;k++) acc[i][j][k]=0.f;
        }
    }

    float4 ra[4], rb[4];
    // ---- prologue: load tile 0 ----
    #pragma unroll
    for (int j=0;j<4;j++) ra[j] = *(const float4*)(arow + akq + 4*j);
    #pragma unroll
    for (int j=0;j<4;j++){
        int col = bn + bnq + 4*j;
        const float* src = B + (size_t)bkl*N + col;
        if (col + 3 < N) rb[j] = *(const float4*)src;
        else {
            rb[j].x = (col+0<N)? src[0]:0.f; rb[j].y = (col+1<N)? src[1]:0.f;
            rb[j].z = (col+2<N)? src[2]:0.f; rb[j].w = (col+3<N)? src[3]:0.f;
        }
    }
    #pragma unroll
    for (int j=0;j<4;j++){
        *(float4*)(sA + arl*36 + akq + 4*j) =
            make_float4(f2t(ra[j].x), f2t(ra[j].y), f2t(ra[j].z), f2t(ra[j].w));
        *(float4*)(sB + bkl*136 + bnq + 4*j) =
            make_float4(f2t(rb[j].x), f2t(rb[j].y), f2t(rb[j].z), f2t(rb[j].w));
    }
    __syncthreads();

    for (int kt = 0; kt < 16; ++kt){
        const int cur = kt & 1;
        if (kt < 15){
            int kb = (kt+1)*32;
            #pragma unroll
            for (int j=0;j<4;j++) ra[j] = *(const float4*)(arow + kb + akq + 4*j);
            #pragma unroll
            for (int j=0;j<4;j++){
                int col = bn + bnq + 4*j;
                const float* src = B + (size_t)(kb + bkl)*N + col;
                if (col + 3 < N) rb[j] = *(const float4*)src;
                else {
                    rb[j].x = (col+0<N)? src[0]:0.f; rb[j].y = (col+1<N)? src[1]:0.f;
                    rb[j].z = (col+2<N)? src[2]:0.f; rb[j].w = (col+3<N)? src[3]:0.f;
                }
            }
        }
        const float* cA = sA + cur*128*36;
        const float* cB = sB + cur*32*136;
        #pragma unroll
        for (int kk = 0; kk < 32; kk += 8){
            unsigned af[4][4];
            #pragma unroll
            for (int ma=0; ma<4; ++ma){
                int mr = wm*64 + ma*16;
                af[ma][0] = bits(cA[(mr+ly  )*36 + kk   + lx]);
                af[ma][1] = bits(cA[(mr+8+ly)*36 + kk   + lx]);
                af[ma][2] = bits(cA[(mr+ly  )*36 + kk+4 + lx]);
                af[ma][3] = bits(cA[(mr+8+ly)*36 + kk+4 + lx]);
            }
            unsigned bf[4][2];
            #pragma unroll
            for (int na=0; na<4; ++na){
                int n0 = wn*32 + na*8;
                bf[na][0] = bits(cB[(kk  +lx)*136 + n0 + ly]);
                bf[na][1] = bits(cB[(kk+4+lx)*136 + n0 + ly]);
            }
            #pragma unroll
            for (int ma=0; ma<4; ++ma) {
                #pragma unroll
                for (int na=0; na<4; ++na)
                    mma8(acc[ma][na], af[ma], bf[na][0], bf[na][1]);
            }
        }
        __syncthreads();
        if (kt < 15){
            const int nxt = (kt+1)&1;
            #pragma unroll
            for (int j=0;j<4;j++){
                *(float4*)(sA + nxt*128*36 + arl*36 + akq + 4*j) =
                    make_float4(f2t(ra[j].x), f2t(ra[j].y), f2t(ra[j].z), f2t(ra[j].w));
                *(float4*)(sB + nxt*32*136 + bkl*136 + bnq + 4*j) =
                    make_float4(f2t(rb[j].x), f2t(rb[j].y), f2t(rb[j].z), f2t(rb[j].w));
            }
            __syncthreads();
        }
    }

    // ---- epilogue: bias + store (float2 pairs; N even so pairs never straddle)
    #pragma unroll
    for (int na=0; na<4; ++na){
        int n0 = bn + wn*32 + na*8 + lx*2;
        if (n0 < N){
            float2 bs = *(const float2*)(bias + n0);
            #pragma unroll
            for (int ma=0; ma<4; ++ma){
                int row = bm + wm*64 + ma*16 + ly;
                float2 v0 = make_float2(acc[ma][na][0] + bs.x, acc[ma][na][1] + bs.y);
                float2 v1 = make_float2(acc[ma][na][2] + bs.x, acc[ma][na][3] + bs.y);
                *(float2*)(C + (size_t)row*N + n0)     = v0;
                *(float2*)(C + (size_t)(row+8)*N + n0) = v1;
            }
        }
    }
}

// ============================================================================
// Persistent GRU recurrence (one launch per layer).
// 32 blocks x 256 threads; block b owns H-columns [16b, 16b+16).
// Weights (Ur|Uz slice, Uht slice) pre-converted to tf32, resident in smem.
// h and z fragments persist in registers across phases/steps (identical mma
// fragment (row,col) mapping in phase A and B). r*h goes through L2 (stcg/ldcg).
// ============================================================================
#define UW_OFF 0
#define UT_OFF (512*40)
#define SH_OFF (512*40 + 512*24)
#define RSMEM_FLOATS (512*40 + 512*24 + 128*132)

__global__ void __launch_bounds__(256) recur_kernel(
    const float* __restrict__ G,     // [70*128, 1536]
    const float* __restrict__ Uh,    // [512, 1024]
    const float* __restrict__ Uht,   // [512, 512]
    const float* __restrict__ h0in,  // [128, 512] initial hidden (this layer)
    float* __restrict__ hall,        // [70, 128, 512]
    float* __restrict__ rhbuf)       // [128, 512]
{
    extern __shared__ float sm[];
    float* sUw = sm + UW_OFF;   // [512][40]  cols 0..15 = Ur(J), 16..31 = Uz(J)
    float* sUt = sm + UT_OFF;   // [512][24]  cols 0..15 = Uht(J)
    float* sH  = sm + SH_OFF;   // [128][132] staging for h / r*h chunks (k=128)

    const int tid = threadIdx.x, w = tid>>5, lane = tid&31;
    const int ly = lane>>2, lx = lane&3;
    const int J0 = blockIdx.x*16;
    const int R0 = w*16;

    // preload + pre-convert weight slices
    for (int i = tid; i < 512*16; i += 256){
        int k = i >> 4, j = i & 15;
        sUw[k*40 + j]      = f2t(__ldg(Uh  + (size_t)k*1024 +       J0 + j));
        sUw[k*40 + 16 + j] = f2t(__ldg(Uh  + (size_t)k*1024 + 512 + J0 + j));
        sUt[k*24 + j]      = f2t(__ldg(Uht + (size_t)k*512  +       J0 + j));
    }

    // init h fragments (positions match mma C-fragment mapping)
    float hreg[2][4], zreg[2][4], whv[2][4];
    #pragma unroll
    for (int a=0;a<2;a++){
        int c = J0 + 8*a + lx*2;
        float2 v0 = *(const float2*)(h0in + (size_t)(R0+ly  )*512 + c);
        float2 v1 = *(const float2*)(h0in + (size_t)(R0+8+ly)*512 + c);
        hreg[a][0]=v0.x; hreg[a][1]=v0.y; hreg[a][2]=v1.x; hreg[a][3]=v1.y;
    }
    __syncthreads();

    for (int t = 0; t < SEQ; ++t){
        const float* hs = t ? (hall + (size_t)(t-1)*BH) : h0in;

        // ---------------- phase A: u = h @ [Ur|Uz] ----------------
        float accR[2][4] = {{0,0,0,0},{0,0,0,0}};
        float accZ[2][4] = {{0,0,0,0},{0,0,0,0}};
        for (int c4 = 0; c4 < 4; ++c4){
            __syncthreads();
            for (int i = tid; i < 128*32; i += 256){
                int r = i >> 5, q = (i & 31) << 2;
                float4 v = __ldcg((const float4*)(hs + (size_t)r*512 + c4*128 + q));
                *(float4*)(sH + r*132 + q) =
                    make_float4(f2t(v.x), f2t(v.y), f2t(v.z), f2t(v.w));
            }
            __syncthreads();
            #pragma unroll
            for (int k8 = 0; k8 < 16; ++k8){
                int kk = k8*8;
                unsigned af[4];
                af[0] = bits(sH[(R0+ly  )*132 + kk   + lx]);
                af[1] = bits(sH[(R0+8+ly)*132 + kk   + lx]);
                af[2] = bits(sH[(R0+ly  )*132 + kk+4 + lx]);
                af[3] = bits(sH[(R0+8+ly)*132 + kk+4 + lx]);
                int kg = c4*128 + kk;
                const float* u0 = sUw + (kg  +lx)*40;
                const float* u1 = sUw + (kg+4+lx)*40;
                mma8(accR[0], af, bits(u0[ly   ]), bits(u1[ly   ]));
                mma8(accR[1], af, bits(u0[8+ly ]), bits(u1[8+ly ]));
                mma8(accZ[0], af, bits(u0[16+ly]), bits(u1[16+ly]));
                mma8(accZ[1], af, bits(u0[24+ly]), bits(u1[24+ly]));
            }
        }
        // gates: r, z; write r*h; keep z, Wh, h in regs
        #pragma unroll
        for (int a=0;a<2;a++){
            int c = J0 + 8*a + lx*2;
            #pragma unroll
            for (int hf=0; hf<2; ++hf){
                int row = R0 + ly + 8*hf;
                int i0 = 2*hf;
                const float* g = G + (size_t)(t*128 + row)*1536 + c;
                float2 wr = *(const float2*)(g);
                float2 wz = *(const float2*)(g + 512);
                float2 wh = *(const float2*)(g + 1024);
                float r0v = sigm(accR[a][i0]   + wr.x);
                float r1v = sigm(accR[a][i0+1] + wr.y);
                zreg[a][i0]   = sigm(accZ[a][i0]   + wz.x);
                zreg[a][i0+1] = sigm(accZ[a][i0+1] + wz.y);
                whv[a][i0]   = wh.x;
                whv[a][i0+1] = wh.y;
                __stcg((float2*)(rhbuf + (size_t)row*512 + c),
                       make_float2(r0v*hreg[a][i0], r1v*hreg[a][i0+1]));
            }
        }
        gridbar(t*2);

        // ---------------- phase B: ht = tanh(Wh + (r*h) @ Uht) ----------------
        float accH[2][4] = {{0,0,0,0},{0,0,0,0}};
        for (int c4 = 0; c4 < 4; ++c4){
            __syncthreads();
            for (int i = tid; i < 128*32; i += 256){
                int r = i >> 5, q = (i & 31) << 2;
                float4 v = __ldcg((const float4*)(rhbuf + (size_t)r*512 + c4*128 + q));
                *(float4*)(sH + r*132 + q) =
                    make_float4(f2t(v.x), f2t(v.y), f2t(v.z), f2t(v.w));
            }
            __syncthreads();
            #pragma unroll
            for (int k8 = 0; k8 < 16; ++k8){
                int kk = k8*8;
                unsigned af[4];
                af[0] = bits(sH[(R0+ly  )*132 + kk   + lx]);
                af[1] = bits(sH[(R0+8+ly)*132 + kk   + lx]);
                af[2] = bits(sH[(R0+ly  )*132 + kk+4 + lx]);
                af[3] = bits(sH[(R0+8+ly)*132 + kk+4 + lx]);
                int kg = c4*128 + kk;
                const float* v0 = sUt + (kg  +lx)*24;
                const float* v1 = sUt + (kg+4+lx)*24;
                mma8(accH[0], af, bits(v0[ly  ]), bits(v1[ly  ]));
                mma8(accH[1], af, bits(v0[8+ly]), bits(v1[8+ly]));
            }
        }
        // update h
        #pragma unroll
        for (int a=0;a<2;a++){
            int c = J0 + 8*a + lx*2;
            #pragma unroll
            for (int hf=0; hf<2; ++hf){
                int row = R0 + ly + 8*hf;
                int i0 = 2*hf;
                float ht0 = tanhf(accH[a][i0]   + whv[a][i0]);
                float ht1 = tanhf(accH[a][i0+1] + whv[a][i0+1]);
                float h0n = hreg[a][i0]   + zreg[a][i0]  *(ht0 - hreg[a][i0]);
                float h1n = hreg[a][i0+1] + zreg[a][i0+1]*(ht1 - hreg[a][i0+1]);
                hreg[a][i0] = h0n; hreg[a][i0+1] = h1n;
                __stcg((float2*)(hall + (size_t)t*BH + (size_t)row*512 + c),
                       make_float2(h0n, h1n));
            }
        }
        gridbar(t*2+1);
    }
}

// ---------------- final hidden copy ------------------------------------------
__global__ void copy_final(const float* __restrict__ h0,
                           const float* __restrict__ h1,
                           float* __restrict__ out){
    int i = blockIdx.x*256 + threadIdx.x;
    if (i < BH){
        out[LOGITS + i]      = h0[(size_t)(SEQ-1)*BH + i];
        out[LOGITS + BH + i] = h1[(size_t)(SEQ-1)*BH + i];
    }
}

// ============================================================================
extern "C" void kernel_launch(void* const* d_in, const int* in_sizes, int n_in,
                              void* d_out, int out_size){
    const int*   inputs = (const int*)  d_in[0];
    const float* hidden = (const float*)d_in[1];
    const float* emb    = (const float*)d_in[2];
    const float* Wx0    = (const float*)d_in[3];
    const float* Uh0    = (const float*)d_in[4];
    const float* Uht0   = (const float*)d_in[5];
    const float* b0     = (const float*)d_in[6];
    const float* Wx1    = (const float*)d_in[7];
    const float* Uh1    = (const float*)d_in[8];
    const float* Uht1   = (const float*)d_in[9];
    const float* b1     = (const float*)d_in[10];
    const float* decW   = (const float*)d_in[11];
    const float* decb   = (const float*)d_in[12];
    float* out = (float*)d_out;

    float *gG, *gh0, *gh1, *grh;
    cudaGetSymbolAddress((void**)&gG,  g_G);
    cudaGetSymbolAddress((void**)&gh0, g_h0);
    cudaGetSymbolAddress((void**)&gh1, g_h1);
    cudaGetSymbolAddress((void**)&grh, g_rh);

    const int GEMM_SMEM = (2*128*36 + 2*32*136)*4;      // 71680
    const int REC_SMEM  = RSMEM_FLOATS*4;               // 198656
    cudaFuncSetAttribute(gemm_tf32,  cudaFuncAttributeMaxDynamicSharedMemorySize, GEMM_SMEM);
    cudaFuncSetAttribute(recur_kernel, cudaFuncAttributeMaxDynamicSharedMemorySize, REC_SMEM);

    // G0 = gather(emb, inputs) @ Wx0 + b0
    gemm_tf32<<<dim3(12,70), 256, GEMM_SMEM>>>(nullptr, Wx0, b0, gG, 3*HID, inputs, emb);
    zero_bars<<<1,256>>>();
    recur_kernel<<<NB_REC, 256, REC_SMEM>>>(gG, Uh0, Uht0, hidden, gh0, grh);
    // G1 = h0_all @ Wx1 + b1
    gemm_tf32<<<dim3(12,70), 256, GEMM_SMEM>>>(gh0, Wx1, b1, gG, 3*HID, nullptr, nullptr);
    zero_bars<<<1,256>>>();
    recur_kernel<<<NB_REC, 256, REC_SMEM>>>(gG, Uh1, Uht1, hidden + BH, gh1, grh);
    // logits = h1_all @ decW + decb   (written straight into d_out)
    gemm_tf32<<<dim3(79,70), 256, GEMM_SMEM>>>(gh1, decW, decb, out, VOCAB, nullptr, nullptr);
    copy_final<<<256,256>>>(gh0, gh1, out);
}

// round 12
// speedup vs baseline: 2.4153x; 2.4153x over previous
#include <cuda_runtime.h>
#include <cuda_bf16.h>
#include <math.h>
#include <stdint.h>

#define SEQ    70
#define BATCH  128
#define HID    512
#define VOCAB  10000
#define MB     (SEQ*BATCH)        /* 8960 */
#define BH     (BATCH*HID)        /* 65536 */
#define LOGITS ((size_t)MB*VOCAB) /* 89,600,000 */
#define NGRID  148                /* one wave: 1 block/SM (198KB smem), <= 152 SMs on GB300 */
#define NWORK  84                 /* GEMM worker blocks */
#define NDEC   (NWORK-12)         /* decoder worker blocks */

// ---------------- device scratch (no runtime allocation allowed) -------------
__device__ float g_G0[(size_t)MB*1536];   // layer0 input projections
__device__ float g_G1[(size_t)MB*1536];   // layer1 input projections
__device__ float g_h0[(size_t)SEQ*BH];
__device__ float g_h1[(size_t)SEQ*BH];
__device__ float g_rh0[BH];
__device__ float g_rh1[BH];
__device__ volatile unsigned g_bar0[160];  // layer0 per-phase group barrier counters
__device__ volatile unsigned g_bar1[160];  // layer1
__device__ volatile unsigned g_g0c[SEQ];   // G0 tile-completion count per step (12 = ready)
__device__ volatile unsigned g_g1c[SEQ];   // G1 tile-completion count per step
__device__ unsigned g_decq;                // decoder tile queue head

// ---------------- helpers ----------------------------------------------------
__device__ __forceinline__ float f2t(float x){
    unsigned u; asm("cvt.rna.tf32.f32 %0, %1;" : "=r"(u) : "f"(x));
    return __uint_as_float(u);
}
__device__ __forceinline__ unsigned bits(float x){ return __float_as_uint(x); }

__device__ __forceinline__ void mma8(float* c, const unsigned* a, unsigned b0, unsigned b1){
    asm volatile(
      "mma.sync.aligned.m16n8k8.row.col.f32.tf32.tf32.f32 "
      "{%0,%1,%2,%3},{%4,%5,%6,%7},{%8,%9},{%0,%1,%2,%3};\n"
      : "+f"(c[0]), "+f"(c[1]), "+f"(c[2]), "+f"(c[3])
      : "r"(a[0]), "r"(a[1]), "r"(a[2]), "r"(a[3]), "r"(b0), "r"(b1));
}
__device__ __forceinline__ float sigm(float x){ return 1.0f/(1.0f + expf(-x)); }

__global__ void zero_ctrs(){
    int i = threadIdx.x;
    if (i < 160){ g_bar0[i] = 0u; g_bar1[i] = 0u; }
    if (i < SEQ){ g_g0c[i] = 0u;  g_g1c[i] = 0u; }
    if (i == 0)  g_decq = 0u;
}

// group barrier among the 32 blocks of one recurrence layer
__device__ __forceinline__ void groupbar(volatile unsigned* bar, int idx){
    __threadfence();
    __syncthreads();
    if (threadIdx.x == 0){
        atomicAdd((unsigned*)&bar[idx], 1u);
        while (bar[idx] < 32u) { }
        __threadfence();
    }
    __syncthreads();
}

// block-wide acquire-wait for a monotone counter to reach v
__device__ __forceinline__ void waitflag(volatile unsigned* f, unsigned v){
    if (threadIdx.x == 0){
        while (*f < v) __nanosleep(128);
        __threadfence();
    }
    __syncthreads();
}

// publish completion of a tile: all stores visible, then count
__device__ __forceinline__ void publish(volatile unsigned* c){
    __threadfence();
    __syncthreads();
    if (threadIdx.x == 0) atomicAdd((unsigned*)c, 1u);
}

// ============================================================================
// One 128x128 output tile of  C = A[128,512] @ B[512,N] + bias,  tf32 mma.
// A rows: Abase + r*512, or gathered gtab[gidx[r]]*512. C points at the tile's
// row base (row 0). 256 threads, 8 warps (2m x 4n), warp tile 64x32, BK=32 x2buf.
// ============================================================================
__device__ void gemm_tile(
    const float* __restrict__ Abase,
    const int* __restrict__ gidx, const float* __restrict__ gtab,
    const float* __restrict__ B, const float* __restrict__ bias,
    float* __restrict__ C, int N, int bn, float* sm)
{
    float* sA = sm;              // [2][128][36]
    float* sB = sm + 2*128*36;   // [2][32][136]

    const int tid = threadIdx.x, w = tid>>5, lane = tid&31;
    const int ly = lane>>2, lx = lane&3;
    const int wm = w>>2, wn = w&3;

    const int arl = tid>>1;
    const int akq = (tid&1)*16;
    const float* arow = gidx ? (gtab + (size_t)__ldg(gidx + arl)*512)
                             : (Abase + (size_t)arl*512);
    const int bkl = tid>>3, bnq = (tid&7)*16;

    float acc[4][4][4];
    #pragma unroll
    for (int i=0;i<4;i++) {
        #pragma unroll
        for (int j=0;j<4;j++) {
            #pragma unroll
            for (int k=0;k<4;k++) acc[i][j][k]=0.f;
        }
    }

    float4 ra[4], rb[4];
    #pragma unroll
    for (int j=0;j<4;j++) ra[j] = *(const float4*)(arow + akq + 4*j);
    #pragma unroll
    for (int j=0;j<4;j++){
        int col = bn + bnq + 4*j;
        const float* src = B + (size_t)bkl*N + col;
        if (col + 3 < N) rb[j] = *(const float4*)src;
        else {
            rb[j].x = (col+0<N)? src[0]:0.f; rb[j].y = (col+1<N)? src[1]:0.f;
            rb[j].z = (col+2<N)? src[2]:0.f; rb[j].w = (col+3<N)? src[3]:0.f;
        }
    }
    #pragma unroll
    for (int j=0;j<4;j++){
        *(float4*)(sA + arl*36 + akq + 4*j) =
            make_float4(f2t(ra[j].x), f2t(ra[j].y), f2t(ra[j].z), f2t(ra[j].w));
        *(float4*)(sB + bkl*136 + bnq + 4*j) =
            make_float4(f2t(rb[j].x), f2t(rb[j].y), f2t(rb[j].z), f2t(rb[j].w));
    }
    __syncthreads();

    for (int kt = 0; kt < 16; ++kt){
        const int cur = kt & 1;
        if (kt < 15){
            int kb = (kt+1)*32;
            #pragma unroll
            for (int j=0;j<4;j++) ra[j] = *(const float4*)(arow + kb + akq + 4*j);
            #pragma unroll
            for (int j=0;j<4;j++){
                int col = bn + bnq + 4*j;
                const float* src = B + (size_t)(kb + bkl)*N + col;
                if (col + 3 < N) rb[j] = *(const float4*)src;
                else {
                    rb[j].x = (col+0<N)? src[0]:0.f; rb[j].y = (col+1<N)? src[1]:0.f;
                    rb[j].z = (col+2<N)? src[2]:0.f; rb[j].w = (col+3<N)? src[3]:0.f;
                }
            }
        }
        const float* cA = sA + cur*128*36;
        const float* cB = sB + cur*32*136;
        #pragma unroll
        for (int kk = 0; kk < 32; kk += 8){
            unsigned af[4][4];
            #pragma unroll
            for (int ma=0; ma<4; ++ma){
                int mr = wm*64 + ma*16;
                af[ma][0] = bits(cA[(mr+ly  )*36 + kk   + lx]);
                af[ma][1] = bits(cA[(mr+8+ly)*36 + kk   + lx]);
                af[ma][2] = bits(cA[(mr+ly  )*36 + kk+4 + lx]);
                af[ma][3] = bits(cA[(mr+8+ly)*36 + kk+4 + lx]);
            }
            unsigned bf[4][2];
            #pragma unroll
            for (int na=0; na<4; ++na){
                int n0 = wn*32 + na*8;
                bf[na][0] = bits(cB[(kk  +lx)*136 + n0 + ly]);
                bf[na][1] = bits(cB[(kk+4+lx)*136 + n0 + ly]);
            }
            #pragma unroll
            for (int ma=0; ma<4; ++ma) {
                #pragma unroll
                for (int na=0; na<4; ++na)
                    mma8(acc[ma][na], af[ma], bf[na][0], bf[na][1]);
            }
        }
        __syncthreads();
        if (kt < 15){
            const int nxt = (kt+1)&1;
            #pragma unroll
            for (int j=0;j<4;j++){
                *(float4*)(sA + nxt*128*36 + arl*36 + akq + 4*j) =
                    make_float4(f2t(ra[j].x), f2t(ra[j].y), f2t(ra[j].z), f2t(ra[j].w));
                *(float4*)(sB + nxt*32*136 + bkl*136 + bnq + 4*j) =
                    make_float4(f2t(rb[j].x), f2t(rb[j].y), f2t(rb[j].z), f2t(rb[j].w));
            }
            __syncthreads();
        }
    }

    #pragma unroll
    for (int na=0; na<4; ++na){
        int n0 = bn + wn*32 + na*8 + lx*2;
        if (n0 < N){
            float2 bs = *(const float2*)(bias + n0);
            #pragma unroll
            for (int ma=0; ma<4; ++ma){
                int row = wm*64 + ma*16 + ly;
                float2 v0 = make_float2(acc[ma][na][0] + bs.x, acc[ma][na][1] + bs.y);
                float2 v1 = make_float2(acc[ma][na][2] + bs.x, acc[ma][na][3] + bs.y);
                *(float2*)(C + (size_t)row*N + n0)     = v0;
                *(float2*)(C + (size_t)(row+8)*N + n0) = v1;
            }
        }
    }
}

// ============================================================================
// GRU recurrence for one layer: 32 blocks, block owns 16 H-columns (J0).
// Weights tf32 in smem for all 70 steps; h/z fragments register-resident.
// Per-step gating: waits readyc[t] >= 12 (input projections G(t) ready).
// ============================================================================
#define UW_OFF 0
#define UT_OFF (512*40)
#define SH_OFF (512*40 + 512*24)
#define RSMEM_FLOATS (512*40 + 512*24 + 128*132)   /* 49664 floats = 198656 B */

__device__ void recur_layer(
    const float* __restrict__ G, const float* __restrict__ Uh,
    const float* __restrict__ Uht, const float* __restrict__ h0in,
    float* __restrict__ hall, float* __restrict__ rhbuf,
    volatile unsigned* bar, volatile unsigned* readyc,
    int J0, float* __restrict__ outh, float* sm)
{
    float* sUw = sm + UW_OFF;   // [512][40]  cols 0..15 = Ur(J), 16..31 = Uz(J)
    float* sUt = sm + UT_OFF;   // [512][24]  cols 0..15 = Uht(J)
    float* sH  = sm + SH_OFF;   // [128][132] staging for h / r*h chunks

    const int tid = threadIdx.x, w = tid>>5, lane = tid&31;
    const int ly = lane>>2, lx = lane&3;
    const int R0 = w*16;

    for (int i = tid; i < 512*16; i += 256){
        int k = i >> 4, j = i & 15;
        sUw[k*40 + j]      = f2t(__ldg(Uh  + (size_t)k*1024 +       J0 + j));
        sUw[k*40 + 16 + j] = f2t(__ldg(Uh  + (size_t)k*1024 + 512 + J0 + j));
        sUt[k*24 + j]      = f2t(__ldg(Uht + (size_t)k*512  +       J0 + j));
    }

    float hreg[2][4], zreg[2][4], whv[2][4];
    #pragma unroll
    for (int a=0;a<2;a++){
        int c = J0 + 8*a + lx*2;
        float2 v0 = *(const float2*)(h0in + (size_t)(R0+ly  )*512 + c);
        float2 v1 = *(const float2*)(h0in + (size_t)(R0+8+ly)*512 + c);
        hreg[a][0]=v0.x; hreg[a][1]=v0.y; hreg[a][2]=v1.x; hreg[a][3]=v1.y;
    }
    __syncthreads();

    for (int t = 0; t < SEQ; ++t){
        waitflag(&readyc[t], 12u);          // G(t) tiles ready
        const float* hs = t ? (hall + (size_t)(t-1)*BH) : h0in;

        // ---------------- phase A: u = h @ [Ur|Uz] ----------------
        float accR[2][4] = {{0,0,0,0},{0,0,0,0}};
        float accZ[2][4] = {{0,0,0,0},{0,0,0,0}};
        for (int c4 = 0; c4 < 4; ++c4){
            __syncthreads();
            for (int i = tid; i < 128*32; i += 256){
                int r = i >> 5, q = (i & 31) << 2;
                float4 v = __ldcg((const float4*)(hs + (size_t)r*512 + c4*128 + q));
                *(float4*)(sH + r*132 + q) =
                    make_float4(f2t(v.x), f2t(v.y), f2t(v.z), f2t(v.w));
            }
            __syncthreads();
            #pragma unroll
            for (int k8 = 0; k8 < 16; ++k8){
                int kk = k8*8;
                unsigned af[4];
                af[0] = bits(sH[(R0+ly  )*132 + kk   + lx]);
                af[1] = bits(sH[(R0+8+ly)*132 + kk   + lx]);
                af[2] = bits(sH[(R0+ly  )*132 + kk+4 + lx]);
                af[3] = bits(sH[(R0+8+ly)*132 + kk+4 + lx]);
                int kg = c4*128 + kk;
                const float* u0 = sUw + (kg  +lx)*40;
                const float* u1 = sUw + (kg+4+lx)*40;
                mma8(accR[0], af, bits(u0[ly   ]), bits(u1[ly   ]));
                mma8(accR[1], af, bits(u0[8+ly ]), bits(u1[8+ly ]));
                mma8(accZ[0], af, bits(u0[16+ly]), bits(u1[16+ly]));
                mma8(accZ[1], af, bits(u0[24+ly]), bits(u1[24+ly]));
            }
        }
        #pragma unroll
        for (int a=0;a<2;a++){
            int c = J0 + 8*a + lx*2;
            #pragma unroll
            for (int hf=0; hf<2; ++hf){
                int row = R0 + ly + 8*hf;
                int i0 = 2*hf;
                const float* g = G + (size_t)(t*128 + row)*1536 + c;
                float2 wr = *(const float2*)(g);
                float2 wz = *(const float2*)(g + 512);
                float2 wh = *(const float2*)(g + 1024);
                float r0v = sigm(accR[a][i0]   + wr.x);
                float r1v = sigm(accR[a][i0+1] + wr.y);
                zreg[a][i0]   = sigm(accZ[a][i0]   + wz.x);
                zreg[a][i0+1] = sigm(accZ[a][i0+1] + wz.y);
                whv[a][i0]   = wh.x;
                whv[a][i0+1] = wh.y;
                __stcg((float2*)(rhbuf + (size_t)row*512 + c),
                       make_float2(r0v*hreg[a][i0], r1v*hreg[a][i0+1]));
            }
        }
        groupbar(bar, t*2);

        // ---------------- phase B: ht = tanh(Wh + (r*h) @ Uht) ----------------
        float accH[2][4] = {{0,0,0,0},{0,0,0,0}};
        for (int c4 = 0; c4 < 4; ++c4){
            __syncthreads();
            for (int i = tid; i < 128*32; i += 256){
                int r = i >> 5, q = (i & 31) << 2;
                float4 v = __ldcg((const float4*)(rhbuf + (size_t)r*512 + c4*128 + q));
                *(float4*)(sH + r*132 + q) =
                    make_float4(f2t(v.x), f2t(v.y), f2t(v.z), f2t(v.w));
            }
            __syncthreads();
            #pragma unroll
            for (int k8 = 0; k8 < 16; ++k8){
                int kk = k8*8;
                unsigned af[4];
                af[0] = bits(sH[(R0+ly  )*132 + kk   + lx]);
                af[1] = bits(sH[(R0+8+ly)*132 + kk   + lx]);
                af[2] = bits(sH[(R0+ly  )*132 + kk+4 + lx]);
                af[3] = bits(sH[(R0+8+ly)*132 + kk+4 + lx]);
                int kg = c4*128 + kk;
                const float* v0 = sUt + (kg  +lx)*24;
                const float* v1 = sUt + (kg+4+lx)*24;
                mma8(accH[0], af, bits(v0[ly  ]), bits(v1[ly  ]));
                mma8(accH[1], af, bits(v0[8+ly]), bits(v1[8+ly]));
            }
        }
        #pragma unroll
        for (int a=0;a<2;a++){
            int c = J0 + 8*a + lx*2;
            #pragma unroll
            for (int hf=0; hf<2; ++hf){
                int row = R0 + ly + 8*hf;
                int i0 = 2*hf;
                float ht0 = tanhf(accH[a][i0]   + whv[a][i0]);
                float ht1 = tanhf(accH[a][i0+1] + whv[a][i0+1]);
                float h0n = hreg[a][i0]   + zreg[a][i0]  *(ht0 - hreg[a][i0]);
                float h1n = hreg[a][i0+1] + zreg[a][i0+1]*(ht1 - hreg[a][i0+1]);
                hreg[a][i0] = h0n; hreg[a][i0+1] = h1n;
                __stcg((float2*)(hall + (size_t)t*BH + (size_t)row*512 + c),
                       make_float2(h0n, h1n));
                if (t == SEQ-1)
                    __stcg((float2*)(outh + (size_t)row*512 + c),
                           make_float2(h0n, h1n));
            }
        }
        groupbar(bar, t*2+1);   // publishes h(t) to consumers (G1 / decoder)
    }
}

// ============================================================================
// GEMM worker: G0 tiles first (per-step publication), then either G1 streaming
// (widx<12) or decoder streaming via atomic tile queue, gated on recurrence.
// ============================================================================
__device__ void worker(
    int widx,
    const int* __restrict__ inputs, const float* __restrict__ emb,
    const float* __restrict__ Wx0, const float* __restrict__ b0,
    const float* __restrict__ Wx1, const float* __restrict__ b1,
    const float* __restrict__ decW, const float* __restrict__ decb,
    float* __restrict__ out, float* sm)
{
    __shared__ unsigned s_tile;

    // ---- stage 1: G0 = gather(emb, inputs) @ Wx0 + b0, 70x12 tiles ----
    for (int id = widx; id < SEQ*12; id += NWORK){
        int t = id / 12, n = id % 12;
        gemm_tile(nullptr, inputs + t*128, emb, Wx0, b0,
                  g_G0 + (size_t)t*128*1536, 1536, n*128, sm);
        publish(&g_g0c[t]);
    }

    if (widx < 12){
        // ---- stage 2a: G1(t) = h0(t) @ Wx1 + b1, one n-tile per worker ----
        const int n = widx;
        for (int t = 0; t < SEQ; ++t){
            waitflag(&g_bar0[2*t+1], 32u);    // h0(t) complete
            gemm_tile(g_h0 + (size_t)t*BH, nullptr, nullptr, Wx1, b1,
                      g_G1 + (size_t)t*128*1536, 1536, n*128, sm);
            publish(&g_g1c[t]);
        }
    } else {
        // ---- stage 2b: logits(t) = h1(t) @ decW + decb, 70x79 tile queue ----
        for (;;){
            __syncthreads();
            if (threadIdx.x == 0) s_tile = atomicAdd(&g_decq, 1u);
            __syncthreads();
            unsigned id = s_tile;
            if (id >= SEQ*79u) break;
            int t = id / 79, n = id % 79;
            waitflag(&g_bar1[2*t+1], 32u);    // h1(t) complete
            gemm_tile(g_h1 + (size_t)t*BH, nullptr, nullptr, decW, decb,
                      out + (size_t)t*128*VOCAB, VOCAB, n*128, sm);
        }
    }
}

// ============================================================================
__global__ void __launch_bounds__(256) mega_kernel(
    const int*   __restrict__ inputs, const float* __restrict__ hidden,
    const float* __restrict__ emb,
    const float* __restrict__ Wx0, const float* __restrict__ Uh0,
    const float* __restrict__ Uht0, const float* __restrict__ b0,
    const float* __restrict__ Wx1, const float* __restrict__ Uh1,
    const float* __restrict__ Uht1, const float* __restrict__ b1,
    const float* __restrict__ decW, const float* __restrict__ decb,
    float* __restrict__ out)
{
    extern __shared__ float sm[];
    const int bid = blockIdx.x;
    if (bid < 32){
        recur_layer(g_G0, Uh0, Uht0, hidden, g_h0, g_rh0,
                    g_bar0, g_g0c, bid*16, out + LOGITS, sm);
    } else if (bid < 64){
        recur_layer(g_G1, Uh1, Uht1, hidden + BH, g_h1, g_rh1,
                    g_bar1, g_g1c, (bid-32)*16, out + LOGITS + BH, sm);
    } else {
        worker(bid - 64, inputs, emb, Wx0, b0, Wx1, b1, decW, decb, out, sm);
    }
}

// ============================================================================
extern "C" void kernel_launch(void* const* d_in, const int* in_sizes, int n_in,
                              void* d_out, int out_size){
    const int*   inputs = (const int*)  d_in[0];
    const float* hidden = (const float*)d_in[1];
    const float* emb    = (const float*)d_in[2];
    const float* Wx0    = (const float*)d_in[3];
    const float* Uh0    = (const float*)d_in[4];
    const float* Uht0   = (const float*)d_in[5];
    const float* b0     = (const float*)d_in[6];
    const float* Wx1    = (const float*)d_in[7];
    const float* Uh1    = (const float*)d_in[8];
    const float* Uht1   = (const float*)d_in[9];
    const float* b1     = (const float*)d_in[10];
    const float* decW   = (const float*)d_in[11];
    const float* decb   = (const float*)d_in[12];
    float* out = (float*)d_out;

    const int MEGA_SMEM = RSMEM_FLOATS*4;   // 198656 B -> 1 block/SM, single wave
    cudaFuncSetAttribute(mega_kernel,
                         cudaFuncAttributeMaxDynamicSharedMemorySize, MEGA_SMEM);

    zero_ctrs<<<1, 256>>>();
    mega_kernel<<<NGRID, 256, MEGA_SMEM>>>(
        inputs, hidden, emb, Wx0, Uh0, Uht0, b0,
        Wx1, Uh1, Uht1, b1, decW, decb, out);
}